// round 9
// baseline (speedup 1.0000x reference)
#include <cuda_runtime.h>
#include <cstdint>
#include <math.h>

#define NUM_EXPERTS 8
#define D_MODEL 1024
#define D_FF 4096
#define GROUPS 4
#define TOKENS 16384
#define CHUNK 2048

// ---------------- scratch (device globals) ----------------
// A-fragment-tiled layouts: [mtile][K/8][128 floats], fragment order inside each 16x8 block.
// B-fragment-tiled layouts: [ntile][K/8][64 floats].
__device__ float g_xr [(size_t)GROUPS * TOKENS * D_MODEL];     // 268 MB  x (A-frag, tf32)
__device__ float g_w1t[(size_t)NUM_EXPERTS * D_FF * D_MODEL];  // 134 MB  w1 (B-frag, tf32)
__device__ float g_w2t[(size_t)NUM_EXPERTS * D_MODEL * D_FF];  // 134 MB  w2 (B-frag, tf32)
__device__ float g_h  [(size_t)GROUPS * TOKENS * D_FF];        // 1 GiB   hidden (A-frag, tf32)

// ---------------- helpers ----------------
__device__ __forceinline__ uint32_t smem_u32(const void* p) {
    uint32_t a;
    asm("{ .reg .u64 t; cvta.to.shared.u64 t, %1; cvt.u32.u64 %0, t; }" : "=r"(a) : "l"(p));
    return a;
}

__device__ __forceinline__ float rna_tf32(float x) {
    uint32_t u;
    asm("cvt.rna.tf32.f32 %0, %1;" : "=r"(u) : "f"(x));
    return __uint_as_float(u);
}

__device__ __forceinline__ void mma_tf32(float* c, const uint32_t* a, const uint32_t* b) {
    asm volatile(
        "mma.sync.aligned.m16n8k8.row.col.f32.tf32.tf32.f32 "
        "{%0,%1,%2,%3}, {%4,%5,%6,%7}, {%8,%9}, {%0,%1,%2,%3};"
        : "+f"(c[0]), "+f"(c[1]), "+f"(c[2]), "+f"(c[3])
        : "r"(a[0]), "r"(a[1]), "r"(a[2]), "r"(a[3]), "r"(b[0]), "r"(b[1]));
}

// ---------------- prep kernels ----------------
// A-frag pack: src row-major [M][K] -> dst [mt][K/8][128], with tf32 RNA rounding.
__global__ void __launch_bounds__(256) prep_A(const float* __restrict__ src,
                                              float* __restrict__ dst, int K) {
    __shared__ float t[16][132];
    const int mt = blockIdx.y, kb = blockIdx.x;
    const int tid = threadIdx.x;
#pragma unroll
    for (int i = 0; i < 8; i++) {
        int lin = i * 256 + tid;
        int r = lin >> 7, c = lin & 127;
        t[r][c] = src[(size_t)(mt * 16 + r) * K + kb * 128 + c];
    }
    __syncthreads();
    float* db = dst + ((size_t)mt * (K >> 3) + kb * 16) * 128;
#pragma unroll
    for (int i = 0; i < 8; i++) {
        int lin = i * 256 + tid;
        int kt = lin >> 7, pos = lin & 127;
        int lane = pos >> 2, reg = pos & 3;
        int gl = lane >> 2, tt = lane & 3;
        int r = gl + (reg & 1) * 8;
        int c = kt * 8 + tt + (reg >> 1) * 4;
        db[lin] = rna_tf32(t[r][c]);
    }
}

// B-frag pack: src row-major [K][N] (per expert) -> dst [nt][K/8][64], tf32 RNA.
__global__ void __launch_bounds__(256) prep_B(const float* __restrict__ src,
                                              float* __restrict__ dst, int K, int N) {
    __shared__ float t[8][260];
    const int kt = blockIdx.y, nb = blockIdx.x, e = blockIdx.z;
    const int tid = threadIdx.x;
    const float* sb = src + (size_t)e * K * N;
    float* db = dst + (size_t)e * (N >> 3) * (K >> 3) * 64;
#pragma unroll
    for (int i = 0; i < 8; i++) {
        int lin = i * 256 + tid;
        int r = lin >> 8, c = lin & 255;
        t[r][c] = sb[(size_t)(kt * 8 + r) * N + nb * 256 + c];
    }
    __syncthreads();
#pragma unroll
    for (int i = 0; i < 8; i++) {
        int lin = i * 256 + tid;
        int ntl = lin >> 6, pos = lin & 63;
        int lane = pos >> 1, reg = pos & 1;
        int n = ntl * 8 + (lane >> 2);
        int k = reg * 4 + (lane & 3);
        size_t d = ((size_t)(nb * 32 + ntl) * (K >> 3) + kt) * 64 + pos;
        db[d] = rna_tf32(t[k][n]);
    }
}

// ---------------- GEMM ----------------
// CTA tile 128x256, Kc=32, 3-stage cp.async pipeline. 8 warps (2M x 4N), warp tile 64x64.
static constexpr int S_A_BYTES = 16384;             // 8 mt * 4 kt * 512B
static constexpr int S_B_BYTES = 32768;             // 32 nt * 4 kt * 256B
static constexpr int S_STAGE   = S_A_BYTES + S_B_BYTES;   // 49152
static constexpr int DSMEM     = 3 * S_STAGE + 1024;      // 148480

__device__ __forceinline__ void load_stage(uint32_t sA, const float* __restrict__ Abase,
                                           const float* __restrict__ Bbase,
                                           int K8, int kc, int tid) {
    const uint32_t sB = sA + S_A_BYTES;
#pragma unroll
    for (int i = 0; i < 4; i++) {                   // A: 1024 x 16B
        int lin = (i << 8) + tid;
        int mt = lin >> 7, rem = lin & 127;
        uint32_t dst = sA + mt * 2048 + rem * 16;
        const void* src = Abase + ((size_t)mt * K8 + kc * 4) * 128 + rem * 4;
        asm volatile("cp.async.cg.shared.global [%0], [%1], 16;" :: "r"(dst), "l"(src));
    }
#pragma unroll
    for (int i = 0; i < 8; i++) {                   // B: 2048 x 16B
        int lin = (i << 8) + tid;
        int nt = lin >> 6, rem = lin & 63;
        uint32_t dst = sB + nt * 1024 + rem * 16;
        const void* src = Bbase + ((size_t)nt * K8 + kc * 4) * 64 + rem * 4;
        asm volatile("cp.async.cg.shared.global [%0], [%1], 16;" :: "r"(dst), "l"(src));
    }
}

template <bool GELU>
__global__ void __launch_bounds__(256)
gemm_tf32(const float* __restrict__ A, const float* __restrict__ B,
          const float* __restrict__ bias, float* __restrict__ C,
          int K, int N) {
    extern __shared__ char smem[];
    const uint32_t sb = smem_u32(smem);
    const int tid = threadIdx.x;
    const int wid = tid >> 5;
    const int lid = tid & 31;
    const int gl = lid >> 2, tt = lid & 3;
    const int wm = wid & 1;                          // 0/1: M half (64 rows)
    const int wn = wid >> 1;                         // 0..3: N quarter (64 cols)

    const int ge = blockIdx.z;
    const int gg = ge >> 3, e = ge & 7;
    const int K8 = K >> 3;
    const long row_base = (long)gg * TOKENS + (long)e * CHUNK + (long)blockIdx.y * 128;
    const float* Abase = A + ((size_t)(row_base >> 4) * K8) * 128;
    const float* Bbase = B + ((size_t)(e * (N >> 3) + blockIdx.x * 32) * K8) * 64;

    float* sbias = (float*)(smem + 3 * S_STAGE);
    sbias[tid] = bias[e * N + blockIdx.x * 256 + tid];

    const int NK = K >> 5;
    load_stage(sb, Abase, Bbase, K8, 0, tid);
    asm volatile("cp.async.commit_group;" ::: "memory");
    load_stage(sb + S_STAGE, Abase, Bbase, K8, 1, tid);
    asm volatile("cp.async.commit_group;" ::: "memory");

    float acc[4][8][4];
#pragma unroll
    for (int i = 0; i < 4; i++)
#pragma unroll
        for (int j = 0; j < 8; j++)
#pragma unroll
            for (int q = 0; q < 4; q++) acc[i][j][q] = 0.0f;

    for (int kc = 0; kc < NK; kc++) {
        asm volatile("cp.async.wait_group 1;" ::: "memory");
        __syncthreads();
        const int nxt = kc + 2;
        if (nxt < NK)
            load_stage(sb + (nxt % 3) * S_STAGE, Abase, Bbase, K8, nxt, tid);
        asm volatile("cp.async.commit_group;" ::: "memory");

        const uint32_t sA = sb + (kc % 3) * S_STAGE;
        const uint32_t sB = sA + S_A_BYTES;
#pragma unroll
        for (int kt = 0; kt < 4; kt++) {
            uint32_t af[4][4], bf[8][2];
#pragma unroll
            for (int mt = 0; mt < 4; mt++) {
                uint32_t a = sA + (uint32_t)(((wm * 4 + mt) * 4 + kt) * 512 + lid * 16);
                asm volatile("ld.shared.v4.b32 {%0,%1,%2,%3}, [%4];"
                             : "=r"(af[mt][0]), "=r"(af[mt][1]), "=r"(af[mt][2]), "=r"(af[mt][3])
                             : "r"(a));
            }
#pragma unroll
            for (int nt = 0; nt < 8; nt++) {
                uint32_t a = sB + (uint32_t)(((wn * 8 + nt) * 4 + kt) * 256 + lid * 8);
                asm volatile("ld.shared.v2.b32 {%0,%1}, [%2];"
                             : "=r"(bf[nt][0]), "=r"(bf[nt][1]) : "r"(a));
            }
#pragma unroll
            for (int mt = 0; mt < 4; mt++)
#pragma unroll
                for (int nt = 0; nt < 8; nt++)
                    mma_tf32(acc[mt][nt], af[mt], bf[nt]);
        }
    }

    // ---- epilogue ----
    const int srcA = (lid & ~3) | (tt >> 1);   // lane holding cols {tt&~1, tt|1}
    const int srcB = srcA + 2;                 // lane holding cols {tt&~1 +4, ...}
#pragma unroll
    for (int mt = 0; mt < 4; mt++) {
#pragma unroll
        for (int nt = 0; nt < 8; nt++) {
            const int col0 = wn * 64 + nt * 8 + 2 * tt;        // cols col0, col0+1
            float v[4];
#pragma unroll
            for (int q = 0; q < 4; q++) {
                float x = acc[mt][nt][q] + sbias[col0 + (q & 1)];
                if (GELU) {
                    x = 0.5f * x * (1.0f + erff(x * 0.70710678118654752f));
                    x = rna_tf32(x);
                }
                v[q] = x;
            }
            if (GELU) {
                // c-frag (16x8 block) == one H A-frag block. Shuffle col pairs
                // {2tt,2tt+1} -> {tt, tt+4}, then fully coalesced 16B/lane store.
                float e0 = __shfl_sync(0xffffffffu, v[0], srcA);
                float e1 = __shfl_sync(0xffffffffu, v[1], srcA);
                float o0 = __shfl_sync(0xffffffffu, v[2], srcA);
                float o1 = __shfl_sync(0xffffffffu, v[3], srcA);
                float f0 = __shfl_sync(0xffffffffu, v[0], srcB);
                float f1 = __shfl_sync(0xffffffffu, v[1], srcB);
                float g0 = __shfl_sync(0xffffffffu, v[2], srcB);
                float g1 = __shfl_sync(0xffffffffu, v[3], srcB);
                float a0 = (tt & 1) ? e1 : e0;   // A[gl][tt]
                float a1 = (tt & 1) ? o1 : o0;   // A[gl+8][tt]
                float a2 = (tt & 1) ? f1 : f0;   // A[gl][tt+4]
                float a3 = (tt & 1) ? g1 : g0;   // A[gl+8][tt+4]
                const size_t Mtile = (size_t)(row_base >> 4) + wm * 4 + mt;
                const int kt2 = blockIdx.x * 32 + wn * 8 + nt;
                float4* dst = reinterpret_cast<float4*>(
                    C + (Mtile * (size_t)(N >> 3) + kt2) * 128 + lid * 4);
                *dst = make_float4(a0, a1, a2, a3);
            } else {
                const int r0 = wm * 64 + mt * 16 + gl;
                long R0 = row_base + r0;
                int c = blockIdx.x * 256 + col0;
                *reinterpret_cast<float2*>(&C[(size_t)R0 * N + c]) = make_float2(v[0], v[1]);
                *reinterpret_cast<float2*>(&C[(size_t)(R0 + 8) * N + c]) = make_float2(v[2], v[3]);
            }
        }
    }
}

// ---------------- launch ----------------
extern "C" void kernel_launch(void* const* d_in, const int* in_sizes, int n_in,
                              void* d_out, int out_size) {
    const float* x  = (const float*)d_in[0];
    const float* w1 = (const float*)d_in[1];
    const float* b1 = (const float*)d_in[2];
    const float* w2 = (const float*)d_in[3];
    const float* b2 = (const float*)d_in[4];
    float* out = (float*)d_out;

    float *p_xr, *p_w1t, *p_w2t, *p_h;
    cudaGetSymbolAddress((void**)&p_xr,  g_xr);
    cudaGetSymbolAddress((void**)&p_w1t, g_w1t);
    cudaGetSymbolAddress((void**)&p_w2t, g_w2t);
    cudaGetSymbolAddress((void**)&p_h,   g_h);

    cudaFuncSetAttribute(gemm_tf32<true>,  cudaFuncAttributeMaxDynamicSharedMemorySize, DSMEM);
    cudaFuncSetAttribute(gemm_tf32<false>, cudaFuncAttributeMaxDynamicSharedMemorySize, DSMEM);

    // pack x into A-frag layout (rows = 65536, K = 1024)
    prep_A<<<dim3(D_MODEL / 128, GROUPS * TOKENS / 16), 256>>>(x, p_xr, D_MODEL);
    // pack w1 [e][1024][4096] (k=d_model, n=d_ff) into B-frag
    prep_B<<<dim3(D_FF / 256, D_MODEL / 8, NUM_EXPERTS), 256>>>(w1, p_w1t, D_MODEL, D_FF);
    // pack w2 [e][4096][1024] (k=d_ff, n=d_model) into B-frag
    prep_B<<<dim3(D_MODEL / 256, D_FF / 8, NUM_EXPERTS), 256>>>(w2, p_w2t, D_FF, D_MODEL);

    // GEMM1: per (g,e): [2048 x 1024] @ [1024 x 4096] + b1, gelu -> H (A-frag layout)
    gemm_tf32<true><<<dim3(D_FF / 256, CHUNK / 128, GROUPS * NUM_EXPERTS), 256, DSMEM>>>(
        p_xr, p_w1t, b1, p_h, D_MODEL, D_FF);
    // GEMM2: per (g,e): [2048 x 4096] @ [4096 x 1024] + b2 -> out (row-major)
    gemm_tf32<false><<<dim3(D_MODEL / 256, CHUNK / 128, GROUPS * NUM_EXPERTS), 256, DSMEM>>>(
        p_h, p_w2t, b2, out, D_FF, D_MODEL);
}

// round 10
// speedup vs baseline: 1.7827x; 1.7827x over previous
#include <cuda_runtime.h>
#include <cstdint>
#include <math.h>

#define NUM_EXPERTS 8
#define D_MODEL 1024
#define D_FF 4096
#define GROUPS 4
#define TOKENS 16384
#define CHUNK 2048

// ---------------- scratch (device globals) ----------------
// A-fragment-tiled layouts: [mtile][K/8][128 floats], fragment order inside each 16x8 block.
// B-fragment-tiled layouts: [ntile][K/8][64 floats].
__device__ float g_xr [(size_t)GROUPS * TOKENS * D_MODEL];     // 268 MB  x (A-frag, tf32)
__device__ float g_w1t[(size_t)NUM_EXPERTS * D_FF * D_MODEL];  // 134 MB  w1 (B-frag, tf32)
__device__ float g_w2t[(size_t)NUM_EXPERTS * D_MODEL * D_FF];  // 134 MB  w2 (B-frag, tf32)
__device__ float g_h  [(size_t)GROUPS * TOKENS * D_FF];        // 1 GiB   hidden (A-frag, tf32)

// ---------------- helpers ----------------
__device__ __forceinline__ uint32_t smem_u32(const void* p) {
    uint32_t a;
    asm("{ .reg .u64 t; cvta.to.shared.u64 t, %1; cvt.u32.u64 %0, t; }" : "=r"(a) : "l"(p));
    return a;
}

__device__ __forceinline__ float rna_tf32(float x) {
    uint32_t u;
    asm("cvt.rna.tf32.f32 %0, %1;" : "=r"(u) : "f"(x));
    return __uint_as_float(u);
}

__device__ __forceinline__ void mma_tf32(float* c, const uint32_t* a, const uint32_t* b) {
    asm volatile(
        "mma.sync.aligned.m16n8k8.row.col.f32.tf32.tf32.f32 "
        "{%0,%1,%2,%3}, {%4,%5,%6,%7}, {%8,%9}, {%0,%1,%2,%3};"
        : "+f"(c[0]), "+f"(c[1]), "+f"(c[2]), "+f"(c[3])
        : "r"(a[0]), "r"(a[1]), "r"(a[2]), "r"(a[3]), "r"(b[0]), "r"(b[1]));
}

// ---------------- prep kernels ----------------
// A-frag pack: src row-major [M][K] -> dst [mt][K/8][128], with tf32 RNA rounding.
__global__ void __launch_bounds__(256) prep_A(const float* __restrict__ src,
                                              float* __restrict__ dst, int K) {
    __shared__ float t[16][132];
    const int mt = blockIdx.y, kb = blockIdx.x;
    const int tid = threadIdx.x;
#pragma unroll
    for (int i = 0; i < 8; i++) {
        int lin = i * 256 + tid;
        int r = lin >> 7, c = lin & 127;
        t[r][c] = src[(size_t)(mt * 16 + r) * K + kb * 128 + c];
    }
    __syncthreads();
    float* db = dst + ((size_t)mt * (K >> 3) + kb * 16) * 128;
#pragma unroll
    for (int i = 0; i < 8; i++) {
        int lin = i * 256 + tid;
        int kt = lin >> 7, pos = lin & 127;
        int lane = pos >> 2, reg = pos & 3;
        int gl = lane >> 2, tt = lane & 3;
        int r = gl + (reg & 1) * 8;
        int c = kt * 8 + tt + (reg >> 1) * 4;
        db[lin] = rna_tf32(t[r][c]);
    }
}

// B-frag pack: src row-major [K][N] (per expert) -> dst [nt][K/8][64], tf32 RNA.
__global__ void __launch_bounds__(256) prep_B(const float* __restrict__ src,
                                              float* __restrict__ dst, int K, int N) {
    __shared__ float t[8][260];
    const int kt = blockIdx.y, nb = blockIdx.x, e = blockIdx.z;
    const int tid = threadIdx.x;
    const float* sb = src + (size_t)e * K * N;
    float* db = dst + (size_t)e * (N >> 3) * (K >> 3) * 64;
#pragma unroll
    for (int i = 0; i < 8; i++) {
        int lin = i * 256 + tid;
        int r = lin >> 8, c = lin & 255;
        t[r][c] = sb[(size_t)(kt * 8 + r) * N + nb * 256 + c];
    }
    __syncthreads();
#pragma unroll
    for (int i = 0; i < 8; i++) {
        int lin = i * 256 + tid;
        int ntl = lin >> 6, pos = lin & 63;
        int lane = pos >> 1, reg = pos & 1;
        int n = ntl * 8 + (lane >> 2);
        int k = reg * 4 + (lane & 3);
        size_t d = ((size_t)(nb * 32 + ntl) * (K >> 3) + kt) * 64 + pos;
        db[d] = rna_tf32(t[k][n]);
    }
}

// ---------------- GEMM ----------------
// CTA tile 128x128, Kc=32, 2-stage cp.async pipeline, 2 CTAs/SM.
// 8 warps (2M x 4N), warp tile 64x32.
static constexpr int S_A_BYTES = 16384;             // 8 mt * 4 kt * 512B
static constexpr int S_B_BYTES = 16384;             // 16 nt * 4 kt * 256B
static constexpr int S_STAGE   = S_A_BYTES + S_B_BYTES;   // 32768
static constexpr int DSMEM     = 2 * S_STAGE + 1024;      // 66560

__device__ __forceinline__ void load_stage(uint32_t sA, const float* __restrict__ Abase,
                                           const float* __restrict__ Bbase,
                                           int K8, int kc, int tid) {
    const uint32_t sB = sA + S_A_BYTES;
#pragma unroll
    for (int i = 0; i < 4; i++) {                   // A: 1024 x 16B
        int lin = (i << 8) + tid;
        int mt = lin >> 7, rem = lin & 127;
        uint32_t dst = sA + mt * 2048 + rem * 16;
        const void* src = Abase + ((size_t)mt * K8 + kc * 4) * 128 + rem * 4;
        asm volatile("cp.async.cg.shared.global [%0], [%1], 16;" :: "r"(dst), "l"(src));
    }
#pragma unroll
    for (int i = 0; i < 4; i++) {                   // B: 1024 x 16B
        int lin = (i << 8) + tid;
        int nt = lin >> 6, rem = lin & 63;
        uint32_t dst = sB + nt * 1024 + rem * 16;
        const void* src = Bbase + ((size_t)nt * K8 + kc * 4) * 64 + rem * 4;
        asm volatile("cp.async.cg.shared.global [%0], [%1], 16;" :: "r"(dst), "l"(src));
    }
}

template <bool GELU>
__global__ void __launch_bounds__(256, 2)
gemm_tf32(const float* __restrict__ A, const float* __restrict__ B,
          const float* __restrict__ bias, float* __restrict__ C,
          int K, int N) {
    extern __shared__ char smem[];
    const uint32_t sb = smem_u32(smem);
    const int tid = threadIdx.x;
    const int wid = tid >> 5;
    const int lid = tid & 31;
    const int gl = lid >> 2, tt = lid & 3;
    const int wm = wid & 1;                          // 0/1: M half (64 rows)
    const int wn = wid >> 1;                         // 0..3: N quarter (32 cols)

    const int ge = blockIdx.z;
    const int gg = ge >> 3, e = ge & 7;
    const int K8 = K >> 3;
    const long row_base = (long)gg * TOKENS + (long)e * CHUNK + (long)blockIdx.y * 128;
    const float* Abase = A + ((size_t)(row_base >> 4) * K8) * 128;
    const float* Bbase = B + ((size_t)(e * (N >> 3) + blockIdx.x * 16) * K8) * 64;

    float* sbias = (float*)(smem + 2 * S_STAGE);
    if (tid < 128) sbias[tid] = bias[e * N + blockIdx.x * 128 + tid];

    const int NK = K >> 5;
    load_stage(sb, Abase, Bbase, K8, 0, tid);
    asm volatile("cp.async.commit_group;" ::: "memory");

    float acc[4][4][4];
#pragma unroll
    for (int i = 0; i < 4; i++)
#pragma unroll
        for (int j = 0; j < 4; j++)
#pragma unroll
            for (int q = 0; q < 4; q++) acc[i][j][q] = 0.0f;

    for (int kc = 0; kc < NK; kc++) {
        asm volatile("cp.async.wait_group 0;" ::: "memory");
        __syncthreads();
        const int nxt = kc + 1;
        if (nxt < NK)
            load_stage(sb + (nxt & 1) * S_STAGE, Abase, Bbase, K8, nxt, tid);
        asm volatile("cp.async.commit_group;" ::: "memory");

        const uint32_t sA = sb + (kc & 1) * S_STAGE;
        const uint32_t sB = sA + S_A_BYTES;
#pragma unroll
        for (int kt = 0; kt < 4; kt++) {
            uint32_t af[4][4], bf[4][2];
#pragma unroll
            for (int mt = 0; mt < 4; mt++) {
                uint32_t a = sA + (uint32_t)(((wm * 4 + mt) * 4 + kt) * 512 + lid * 16);
                asm volatile("ld.shared.v4.b32 {%0,%1,%2,%3}, [%4];"
                             : "=r"(af[mt][0]), "=r"(af[mt][1]), "=r"(af[mt][2]), "=r"(af[mt][3])
                             : "r"(a));
            }
#pragma unroll
            for (int nt = 0; nt < 4; nt++) {
                uint32_t a = sB + (uint32_t)(((wn * 4 + nt) * 4 + kt) * 256 + lid * 8);
                asm volatile("ld.shared.v2.b32 {%0,%1}, [%2];"
                             : "=r"(bf[nt][0]), "=r"(bf[nt][1]) : "r"(a));
            }
#pragma unroll
            for (int mt = 0; mt < 4; mt++)
#pragma unroll
                for (int nt = 0; nt < 4; nt++)
                    mma_tf32(acc[mt][nt], af[mt], bf[nt]);
        }
    }

    // ---- epilogue ----
    const int srcA = (lid & ~3) | (tt >> 1);   // lane holding cols {tt&~1, tt|1}
    const int srcB = srcA + 2;                 // lane holding cols {(tt&~1)+4, ...}
#pragma unroll
    for (int mt = 0; mt < 4; mt++) {
#pragma unroll
        for (int nt = 0; nt < 4; nt++) {
            const int col0 = wn * 32 + nt * 8 + 2 * tt;        // cols col0, col0+1
            float v[4];
#pragma unroll
            for (int q = 0; q < 4; q++) {
                float x = acc[mt][nt][q] + sbias[col0 + (q & 1)];
                if (GELU) {
                    x = 0.5f * x * (1.0f + erff(x * 0.70710678118654752f));
                    x = rna_tf32(x);
                }
                v[q] = x;
            }
            if (GELU) {
                // c-frag (16x8 block) == one H A-frag block. Shuffle col pairs
                // {2tt,2tt+1} -> {tt, tt+4}, then fully coalesced 16B/lane store.
                float e0 = __shfl_sync(0xffffffffu, v[0], srcA);
                float e1 = __shfl_sync(0xffffffffu, v[1], srcA);
                float o0 = __shfl_sync(0xffffffffu, v[2], srcA);
                float o1 = __shfl_sync(0xffffffffu, v[3], srcA);
                float f0 = __shfl_sync(0xffffffffu, v[0], srcB);
                float f1 = __shfl_sync(0xffffffffu, v[1], srcB);
                float g0 = __shfl_sync(0xffffffffu, v[2], srcB);
                float g1 = __shfl_sync(0xffffffffu, v[3], srcB);
                float a0 = (tt & 1) ? e1 : e0;   // H[gl][tt]
                float a1 = (tt & 1) ? o1 : o0;   // H[gl+8][tt]
                float a2 = (tt & 1) ? f1 : f0;   // H[gl][tt+4]
                float a3 = (tt & 1) ? g1 : g0;   // H[gl+8][tt+4]
                const size_t Mtile = (size_t)(row_base >> 4) + wm * 4 + mt;
                const int kt2 = blockIdx.x * 16 + wn * 4 + nt;
                float4* dst = reinterpret_cast<float4*>(
                    C + (Mtile * (size_t)(N >> 3) + kt2) * 128 + lid * 4);
                *dst = make_float4(a0, a1, a2, a3);
            } else {
                const int r0 = wm * 64 + mt * 16 + gl;
                long R0 = row_base + r0;
                int c = blockIdx.x * 128 + col0;
                *reinterpret_cast<float2*>(&C[(size_t)R0 * N + c]) = make_float2(v[0], v[1]);
                *reinterpret_cast<float2*>(&C[(size_t)(R0 + 8) * N + c]) = make_float2(v[2], v[3]);
            }
        }
    }
}

// ---------------- launch ----------------
extern "C" void kernel_launch(void* const* d_in, const int* in_sizes, int n_in,
                              void* d_out, int out_size) {
    const float* x  = (const float*)d_in[0];
    const float* w1 = (const float*)d_in[1];
    const float* b1 = (const float*)d_in[2];
    const float* w2 = (const float*)d_in[3];
    const float* b2 = (const float*)d_in[4];
    float* out = (float*)d_out;

    float *p_xr, *p_w1t, *p_w2t, *p_h;
    cudaGetSymbolAddress((void**)&p_xr,  g_xr);
    cudaGetSymbolAddress((void**)&p_w1t, g_w1t);
    cudaGetSymbolAddress((void**)&p_w2t, g_w2t);
    cudaGetSymbolAddress((void**)&p_h,   g_h);

    cudaFuncSetAttribute(gemm_tf32<true>,  cudaFuncAttributeMaxDynamicSharedMemorySize, DSMEM);
    cudaFuncSetAttribute(gemm_tf32<false>, cudaFuncAttributeMaxDynamicSharedMemorySize, DSMEM);

    // pack x into A-frag layout (rows = 65536, K = 1024)
    prep_A<<<dim3(D_MODEL / 128, GROUPS * TOKENS / 16), 256>>>(x, p_xr, D_MODEL);
    // pack w1 [e][1024][4096] (k=d_model, n=d_ff) into B-frag
    prep_B<<<dim3(D_FF / 256, D_MODEL / 8, NUM_EXPERTS), 256>>>(w1, p_w1t, D_MODEL, D_FF);
    // pack w2 [e][4096][1024] (k=d_ff, n=d_model) into B-frag
    prep_B<<<dim3(D_MODEL / 256, D_FF / 8, NUM_EXPERTS), 256>>>(w2, p_w2t, D_FF, D_MODEL);

    // GEMM1: per (g,e): [2048 x 1024] @ [1024 x 4096] + b1, gelu -> H (A-frag layout)
    gemm_tf32<true><<<dim3(D_FF / 128, CHUNK / 128, GROUPS * NUM_EXPERTS), 256, DSMEM>>>(
        p_xr, p_w1t, b1, p_h, D_MODEL, D_FF);
    // GEMM2: per (g,e): [2048 x 4096] @ [4096 x 1024] + b2 -> out (row-major)
    gemm_tf32<false><<<dim3(D_MODEL / 128, CHUNK / 128, GROUPS * NUM_EXPERTS), 256, DSMEM>>>(
        p_h, p_w2t, b2, out, D_FF, D_MODEL);
}

// round 11
// speedup vs baseline: 3.3794x; 1.8957x over previous
#include <cuda_runtime.h>
#include <cuda_fp16.h>
#include <cstdint>
#include <math.h>

#define NUM_EXPERTS 8
#define D_MODEL 1024
#define D_FF 4096
#define GROUPS 4
#define TOKENS 16384
#define CHUNK 2048

// ---------------- scratch (device globals) ----------------
// fp16 fragment-tiled layouts (u32 = half2):
//  A-frag: [mtile(16 rows)][K/16][128 u32]  (16x16 block, lane*4 -> lds.128)
//  B-frag: [ntile(8 cols)][K/16][64 u32]    (16x8 block,  lane*2 -> lds.64)
__device__ uint32_t g_xr [(size_t)(GROUPS * TOKENS / 16) * (D_MODEL / 16) * 128]; // 134 MB
__device__ uint32_t g_w1t[(size_t)NUM_EXPERTS * (D_FF / 8) * (D_MODEL / 16) * 64]; // 67 MB
__device__ uint32_t g_w2t[(size_t)NUM_EXPERTS * (D_MODEL / 8) * (D_FF / 16) * 64]; // 67 MB
__device__ uint32_t g_h  [(size_t)(GROUPS * TOKENS / 16) * (D_FF / 16) * 128];     // 536 MB

// ---------------- helpers ----------------
__device__ __forceinline__ uint32_t smem_u32(const void* p) {
    uint32_t a;
    asm("{ .reg .u64 t; cvta.to.shared.u64 t, %1; cvt.u32.u64 %0, t; }" : "=r"(a) : "l"(p));
    return a;
}

__device__ __forceinline__ uint32_t pack_h2(float lo, float hi) {
    uint32_t u;
    asm("cvt.rn.f16x2.f32 %0, %1, %2;" : "=r"(u) : "f"(hi), "f"(lo));  // d = {hi, lo}
    return u;
}

__device__ __forceinline__ void mma_fp16(float* c, const uint32_t* a, const uint32_t* b) {
    asm volatile(
        "mma.sync.aligned.m16n8k16.row.col.f32.f16.f16.f32 "
        "{%0,%1,%2,%3}, {%4,%5,%6,%7}, {%8,%9}, {%0,%1,%2,%3};"
        : "+f"(c[0]), "+f"(c[1]), "+f"(c[2]), "+f"(c[3])
        : "r"(a[0]), "r"(a[1]), "r"(a[2]), "r"(a[3]), "r"(b[0]), "r"(b[1]));
}

// ---------------- prep kernels ----------------
// A-frag pack: src row-major [M][K] f32 -> dst u32 [mt][K/16][128], fp16 RN.
// Block: 16 rows x 128 cols (one mtile x 8 k-blocks).
__global__ void __launch_bounds__(256) prep_A(const float* __restrict__ src,
                                              uint32_t* __restrict__ dst, int K) {
    __shared__ float t[16][132];
    const int mt = blockIdx.y, kb8 = blockIdx.x;
    const int tid = threadIdx.x;
    const int K16 = K >> 4;
#pragma unroll
    for (int i = 0; i < 8; i++) {
        int lin = i * 256 + tid;
        int r = lin >> 7, c = lin & 127;
        t[r][c] = src[(size_t)(mt * 16 + r) * K + kb8 * 128 + c];
    }
    __syncthreads();
#pragma unroll
    for (int i = 0; i < 4; i++) {
        int lin = i * 256 + tid;                 // 1024 u32 outputs
        int kbl = lin >> 7, pos = lin & 127;
        int lane = pos >> 2, reg = pos & 3;
        int gl = lane >> 2, tt = lane & 3;
        int r = gl + (reg & 1) * 8;
        int kl = kbl * 16 + 2 * tt + (reg >> 1) * 8;
        dst[((size_t)mt * K16 + kb8 * 8 + kbl) * 128 + pos] = pack_h2(t[r][kl], t[r][kl + 1]);
    }
}

// B-frag pack: src row-major [K][N] f32 (per expert) -> dst u32 [nt][K/16][64], fp16 RN.
// Block: 16 k-rows x 256 n-cols (one k-block x 32 nt). blockIdx.z = expert.
__global__ void __launch_bounds__(256) prep_B(const float* __restrict__ src,
                                              uint32_t* __restrict__ dst, int K, int N) {
    __shared__ float t[16][260];
    const int kb = blockIdx.y, nb = blockIdx.x, e = blockIdx.z;
    const int tid = threadIdx.x;
    const int K16 = K >> 4;
    const float* sp = src + (size_t)e * K * N;
    uint32_t* dp = dst + (size_t)e * (N >> 3) * K16 * 64;
#pragma unroll
    for (int i = 0; i < 16; i++) {
        int lin = i * 256 + tid;
        int r = lin >> 8, c = lin & 255;
        t[r][c] = sp[(size_t)(kb * 16 + r) * N + nb * 256 + c];
    }
    __syncthreads();
#pragma unroll
    for (int i = 0; i < 8; i++) {
        int lin = i * 256 + tid;                 // 2048 u32 outputs
        int ntl = lin >> 6, pos = lin & 63;
        int lane = pos >> 1, reg = pos & 1;
        int gl = lane >> 2, tt = lane & 3;
        int n = ntl * 8 + gl;
        int kl = 2 * tt + reg * 8;
        dp[((size_t)(nb * 32 + ntl) * K16 + kb) * 64 + pos] = pack_h2(t[kl][n], t[kl + 1][n]);
    }
}

// ---------------- GEMM ----------------
// CTA tile 128x128, Kc=64 (4 kt of K=16), 2-stage cp.async pipeline, 2 CTAs/SM.
// 8 warps (2M x 4N), warp tile 64x32.
static constexpr int S_A_BYTES = 16384;             // 8 mt * 4 kt * 512B
static constexpr int S_B_BYTES = 16384;             // 16 nt * 4 kt * 256B
static constexpr int S_STAGE   = S_A_BYTES + S_B_BYTES;   // 32768
static constexpr int DSMEM     = 2 * S_STAGE + 1024;      // 66560

__device__ __forceinline__ void load_stage(uint32_t sA, const uint32_t* __restrict__ Abase,
                                           const uint32_t* __restrict__ Bbase,
                                           int K16, int kc, int tid) {
    const uint32_t sB = sA + S_A_BYTES;
#pragma unroll
    for (int i = 0; i < 4; i++) {                   // A: 1024 x 16B
        int lin = (i << 8) + tid;
        int blk = lin >> 5, c = lin & 31;           // blk = mt*4+kt
        uint32_t dst = sA + blk * 512 + c * 16;
        const void* src = Abase + ((size_t)(blk >> 2) * K16 + kc * 4 + (blk & 3)) * 128 + c * 4;
        asm volatile("cp.async.cg.shared.global [%0], [%1], 16;" :: "r"(dst), "l"(src));
    }
#pragma unroll
    for (int i = 0; i < 4; i++) {                   // B: 1024 x 16B
        int lin = (i << 8) + tid;
        int blk = lin >> 4, c = lin & 15;           // blk = nt*4+kt
        uint32_t dst = sB + blk * 256 + c * 16;
        const void* src = Bbase + ((size_t)(blk >> 2) * K16 + kc * 4 + (blk & 3)) * 64 + c * 4;
        asm volatile("cp.async.cg.shared.global [%0], [%1], 16;" :: "r"(dst), "l"(src));
    }
}

template <bool GELU>
__global__ void __launch_bounds__(256, 2)
gemm_fp16(const uint32_t* __restrict__ A, const uint32_t* __restrict__ B,
          const float* __restrict__ bias, void* __restrict__ Cv,
          int K, int N) {
    extern __shared__ char smem[];
    const uint32_t sb = smem_u32(smem);
    const int tid = threadIdx.x;
    const int wid = tid >> 5;
    const int lid = tid & 31;
    const int gl = lid >> 2, tt = lid & 3;
    const int wm = wid & 1;                          // 0/1: M half (64 rows)
    const int wn = wid >> 1;                         // 0..3: N quarter (32 cols)

    const int ge = blockIdx.z;
    const int gg = ge >> 3, e = ge & 7;
    const int K16 = K >> 4;
    const long row_base = (long)gg * TOKENS + (long)e * CHUNK + (long)blockIdx.y * 128;
    const uint32_t* Abase = A + (size_t)(row_base >> 4) * K16 * 128;
    const uint32_t* Bbase = B + (size_t)(e * (N >> 3) + blockIdx.x * 16) * K16 * 64;

    float* sbias = (float*)(smem + 2 * S_STAGE);
    if (tid < 128) sbias[tid] = bias[e * N + blockIdx.x * 128 + tid];

    const int NK = K >> 6;
    load_stage(sb, Abase, Bbase, K16, 0, tid);
    asm volatile("cp.async.commit_group;" ::: "memory");

    float acc[4][4][4];
#pragma unroll
    for (int i = 0; i < 4; i++)
#pragma unroll
        for (int j = 0; j < 4; j++)
#pragma unroll
            for (int q = 0; q < 4; q++) acc[i][j][q] = 0.0f;

    for (int kc = 0; kc < NK; kc++) {
        asm volatile("cp.async.wait_group 0;" ::: "memory");
        __syncthreads();
        const int nxt = kc + 1;
        if (nxt < NK)
            load_stage(sb + (nxt & 1) * S_STAGE, Abase, Bbase, K16, nxt, tid);
        asm volatile("cp.async.commit_group;" ::: "memory");

        const uint32_t sA = sb + (kc & 1) * S_STAGE;
        const uint32_t sB = sA + S_A_BYTES;
#pragma unroll
        for (int kt = 0; kt < 4; kt++) {
            uint32_t af[4][4], bf[4][2];
#pragma unroll
            for (int mt = 0; mt < 4; mt++) {
                uint32_t a = sA + (uint32_t)((((wm * 4 + mt) * 4 + kt) * 512) + lid * 16);
                asm volatile("ld.shared.v4.b32 {%0,%1,%2,%3}, [%4];"
                             : "=r"(af[mt][0]), "=r"(af[mt][1]), "=r"(af[mt][2]), "=r"(af[mt][3])
                             : "r"(a));
            }
#pragma unroll
            for (int nt = 0; nt < 4; nt++) {
                uint32_t a = sB + (uint32_t)((((wn * 4 + nt) * 4 + kt) * 256) + lid * 8);
                asm volatile("ld.shared.v2.b32 {%0,%1}, [%2];"
                             : "=r"(bf[nt][0]), "=r"(bf[nt][1]) : "r"(a));
            }
#pragma unroll
            for (int mt = 0; mt < 4; mt++)
#pragma unroll
                for (int nt = 0; nt < 4; nt++)
                    mma_fp16(acc[mt][nt], af[mt], bf[nt]);
        }
    }

    // ---- epilogue ----
#pragma unroll
    for (int mt = 0; mt < 4; mt++) {
        if (GELU) {
            uint32_t* C = (uint32_t*)Cv;
            // Two adjacent nt blocks (16 H-cols) form one fp16 A-frag block of H.
            // Lane's own c-frags pack directly: no shuffles needed.
#pragma unroll
            for (int j = 0; j < 2; j++) {
                float v[2][4];
#pragma unroll
                for (int h = 0; h < 2; h++) {
                    const int nt = 2 * j + h;
                    const int col0 = wn * 32 + nt * 8 + 2 * tt;
#pragma unroll
                    for (int q = 0; q < 4; q++) {
                        float x = acc[mt][nt][q] + sbias[col0 + (q & 1)];
                        x = 0.5f * x * (1.0f + erff(x * 0.70710678118654752f));
                        v[h][q] = x;
                    }
                }
                uint32_t p0 = pack_h2(v[0][0], v[0][1]);   // row gl,   k 2tt,2tt+1
                uint32_t p1 = pack_h2(v[0][2], v[0][3]);   // row gl+8, k 2tt,2tt+1
                uint32_t p2 = pack_h2(v[1][0], v[1][1]);   // row gl,   k 2tt+8,2tt+9
                uint32_t p3 = pack_h2(v[1][2], v[1][3]);   // row gl+8, k 2tt+8,2tt+9
                const size_t Mtile = (size_t)(row_base >> 4) + wm * 4 + mt;
                const int kb2 = blockIdx.x * 8 + wn * 2 + j;
                uint4* dst = reinterpret_cast<uint4*>(
                    C + (Mtile * (size_t)(N >> 4) + kb2) * 128 + lid * 4);
                *dst = make_uint4(p0, p1, p2, p3);
            }
        } else {
            float* C = (float*)Cv;
#pragma unroll
            for (int nt = 0; nt < 4; nt++) {
                const int col0 = wn * 32 + nt * 8 + 2 * tt;
                float v[4];
#pragma unroll
                for (int q = 0; q < 4; q++)
                    v[q] = acc[mt][nt][q] + sbias[col0 + (q & 1)];
                const int r0 = wm * 64 + mt * 16 + gl;
                long R0 = row_base + r0;
                int c = blockIdx.x * 128 + col0;
                *reinterpret_cast<float2*>(&C[(size_t)R0 * N + c]) = make_float2(v[0], v[1]);
                *reinterpret_cast<float2*>(&C[(size_t)(R0 + 8) * N + c]) = make_float2(v[2], v[3]);
            }
        }
    }
}

// ---------------- launch ----------------
extern "C" void kernel_launch(void* const* d_in, const int* in_sizes, int n_in,
                              void* d_out, int out_size) {
    const float* x  = (const float*)d_in[0];
    const float* w1 = (const float*)d_in[1];
    const float* b1 = (const float*)d_in[2];
    const float* w2 = (const float*)d_in[3];
    const float* b2 = (const float*)d_in[4];
    float* out = (float*)d_out;

    uint32_t *p_xr, *p_w1t, *p_w2t, *p_h;
    cudaGetSymbolAddress((void**)&p_xr,  g_xr);
    cudaGetSymbolAddress((void**)&p_w1t, g_w1t);
    cudaGetSymbolAddress((void**)&p_w2t, g_w2t);
    cudaGetSymbolAddress((void**)&p_h,   g_h);

    cudaFuncSetAttribute(gemm_fp16<true>,  cudaFuncAttributeMaxDynamicSharedMemorySize, DSMEM);
    cudaFuncSetAttribute(gemm_fp16<false>, cudaFuncAttributeMaxDynamicSharedMemorySize, DSMEM);

    // pack x into fp16 A-frag layout (65536 rows, K=1024)
    prep_A<<<dim3(D_MODEL / 128, GROUPS * TOKENS / 16), 256>>>(x, p_xr, D_MODEL);
    // pack w1 [e][1024][4096] (k=d_model, n=d_ff) into fp16 B-frag
    prep_B<<<dim3(D_FF / 256, D_MODEL / 16, NUM_EXPERTS), 256>>>(w1, p_w1t, D_MODEL, D_FF);
    // pack w2 [e][4096][1024] (k=d_ff, n=d_model) into fp16 B-frag
    prep_B<<<dim3(D_MODEL / 256, D_FF / 16, NUM_EXPERTS), 256>>>(w2, p_w2t, D_FF, D_MODEL);

    // GEMM1: per (g,e): [2048 x 1024] @ [1024 x 4096] + b1, gelu -> H (fp16 A-frag)
    gemm_fp16<true><<<dim3(D_FF / 128, CHUNK / 128, GROUPS * NUM_EXPERTS), 256, DSMEM>>>(
        p_xr, p_w1t, b1, p_h, D_MODEL, D_FF);
    // GEMM2: per (g,e): [2048 x 4096] @ [4096 x 1024] + b2 -> out (row-major f32)
    gemm_fp16<false><<<dim3(D_MODEL / 128, CHUNK / 128, GROUPS * NUM_EXPERTS), 256, DSMEM>>>(
        p_h, p_w2t, b2, out, D_FF, D_MODEL);
}

// round 12
// speedup vs baseline: 3.3856x; 1.0018x over previous
#include <cuda_runtime.h>
#include <cuda_fp16.h>
#include <cstdint>
#include <math.h>

#define NUM_EXPERTS 8
#define D_MODEL 1024
#define D_FF 4096
#define GROUPS 4
#define TOKENS 16384
#define CHUNK 2048

// ---------------- scratch (device globals) ----------------
// fp16 fragment-tiled layouts (u32 = half2):
//  A-frag: [mtile(16 rows)][K/16][128 u32]  (16x16 block, lane*4 -> lds.128)
//  B-frag: [ntile(8 cols)][K/16][64 u32]    (16x8 block,  lane*2 -> lds.64)
__device__ uint32_t g_xr [(size_t)(GROUPS * TOKENS / 16) * (D_MODEL / 16) * 128]; // 134 MB
__device__ uint32_t g_w1t[(size_t)NUM_EXPERTS * (D_FF / 8) * (D_MODEL / 16) * 64]; // 67 MB
__device__ uint32_t g_w2t[(size_t)NUM_EXPERTS * (D_MODEL / 8) * (D_FF / 16) * 64]; // 67 MB
__device__ uint32_t g_h  [(size_t)(GROUPS * TOKENS / 16) * (D_FF / 16) * 128];     // 536 MB

// ---------------- helpers ----------------
__device__ __forceinline__ uint32_t smem_u32(const void* p) {
    uint32_t a;
    asm("{ .reg .u64 t; cvta.to.shared.u64 t, %1; cvt.u32.u64 %0, t; }" : "=r"(a) : "l"(p));
    return a;
}

__device__ __forceinline__ uint32_t pack_h2(float lo, float hi) {
    uint32_t u;
    asm("cvt.rn.f16x2.f32 %0, %1, %2;" : "=r"(u) : "f"(hi), "f"(lo));  // d = {hi, lo}
    return u;
}

__device__ __forceinline__ void mma_fp16(float* c, const uint32_t* a, const uint32_t* b) {
    asm volatile(
        "mma.sync.aligned.m16n8k16.row.col.f32.f16.f16.f32 "
        "{%0,%1,%2,%3}, {%4,%5,%6,%7}, {%8,%9}, {%0,%1,%2,%3};"
        : "+f"(c[0]), "+f"(c[1]), "+f"(c[2]), "+f"(c[3])
        : "r"(a[0]), "r"(a[1]), "r"(a[2]), "r"(a[3]), "r"(b[0]), "r"(b[1]));
}

// ---------------- prep kernels ----------------
// A-frag pack: src row-major [M][K] f32 -> dst u32 [mt][K/16][128], fp16 RN.
__global__ void __launch_bounds__(256) prep_A(const float* __restrict__ src,
                                              uint32_t* __restrict__ dst, int K) {
    __shared__ float t[16][132];
    const int mt = blockIdx.y, kb8 = blockIdx.x;
    const int tid = threadIdx.x;
    const int K16 = K >> 4;
#pragma unroll
    for (int i = 0; i < 8; i++) {
        int lin = i * 256 + tid;
        int r = lin >> 7, c = lin & 127;
        t[r][c] = src[(size_t)(mt * 16 + r) * K + kb8 * 128 + c];
    }
    __syncthreads();
#pragma unroll
    for (int i = 0; i < 4; i++) {
        int lin = i * 256 + tid;                 // 1024 u32 outputs
        int kbl = lin >> 7, pos = lin & 127;
        int lane = pos >> 2, reg = pos & 3;
        int gl = lane >> 2, tt = lane & 3;
        int r = gl + (reg & 1) * 8;
        int kl = kbl * 16 + 2 * tt + (reg >> 1) * 8;
        dst[((size_t)mt * K16 + kb8 * 8 + kbl) * 128 + pos] = pack_h2(t[r][kl], t[r][kl + 1]);
    }
}

// B-frag pack: src row-major [K][N] f32 (per expert) -> dst u32 [nt][K/16][64], fp16 RN.
__global__ void __launch_bounds__(256) prep_B(const float* __restrict__ src,
                                              uint32_t* __restrict__ dst, int K, int N) {
    __shared__ float t[16][260];
    const int kb = blockIdx.y, nb = blockIdx.x, e = blockIdx.z;
    const int tid = threadIdx.x;
    const int K16 = K >> 4;
    const float* sp = src + (size_t)e * K * N;
    uint32_t* dp = dst + (size_t)e * (N >> 3) * K16 * 64;
#pragma unroll
    for (int i = 0; i < 16; i++) {
        int lin = i * 256 + tid;
        int r = lin >> 8, c = lin & 255;
        t[r][c] = sp[(size_t)(kb * 16 + r) * N + nb * 256 + c];
    }
    __syncthreads();
#pragma unroll
    for (int i = 0; i < 8; i++) {
        int lin = i * 256 + tid;                 // 2048 u32 outputs
        int ntl = lin >> 6, pos = lin & 63;
        int lane = pos >> 1, reg = pos & 1;
        int gl = lane >> 2, tt = lane & 3;
        int n = ntl * 8 + gl;
        int kl = 2 * tt + reg * 8;
        dp[((size_t)(nb * 32 + ntl) * K16 + kb) * 64 + pos] = pack_h2(t[kl][n], t[kl + 1][n]);
    }
}

// ---------------- GEMM ----------------
// CTA tile 128x128, Kc=64 (4 kt of K=16), 3-stage cp.async pipeline, 2 CTAs/SM.
// 8 warps (2M x 4N), warp tile 64x32.
static constexpr int S_A_BYTES = 16384;             // 8 mt * 4 kt * 512B
static constexpr int S_B_BYTES = 16384;             // 16 nt * 4 kt * 256B
static constexpr int S_STAGE   = S_A_BYTES + S_B_BYTES;   // 32768
static constexpr int DSMEM     = 3 * S_STAGE + 1024;      // 99328 (x2 CTA = 195KB < 228KB)

__device__ __forceinline__ void load_stage(uint32_t sA, const uint32_t* __restrict__ Abase,
                                           const uint32_t* __restrict__ Bbase,
                                           int K16, int kc, int tid) {
    const uint32_t sB = sA + S_A_BYTES;
#pragma unroll
    for (int i = 0; i < 4; i++) {                   // A: 1024 x 16B
        int lin = (i << 8) + tid;
        int blk = lin >> 5, c = lin & 31;           // blk = mt*4+kt
        uint32_t dst = sA + blk * 512 + c * 16;
        const void* src = Abase + ((size_t)(blk >> 2) * K16 + kc * 4 + (blk & 3)) * 128 + c * 4;
        asm volatile("cp.async.cg.shared.global [%0], [%1], 16;" :: "r"(dst), "l"(src));
    }
#pragma unroll
    for (int i = 0; i < 4; i++) {                   // B: 1024 x 16B
        int lin = (i << 8) + tid;
        int blk = lin >> 4, c = lin & 15;           // blk = nt*4+kt
        uint32_t dst = sB + blk * 256 + c * 16;
        const void* src = Bbase + ((size_t)(blk >> 2) * K16 + kc * 4 + (blk & 3)) * 64 + c * 4;
        asm volatile("cp.async.cg.shared.global [%0], [%1], 16;" :: "r"(dst), "l"(src));
    }
}

template <bool GELU>
__global__ void __launch_bounds__(256, 2)
gemm_fp16(const uint32_t* __restrict__ A, const uint32_t* __restrict__ B,
          const float* __restrict__ bias, void* __restrict__ Cv,
          int K, int N) {
    extern __shared__ char smem[];
    const uint32_t sb = smem_u32(smem);
    const int tid = threadIdx.x;
    const int wid = tid >> 5;
    const int lid = tid & 31;
    const int gl = lid >> 2, tt = lid & 3;
    const int wm = wid & 1;                          // 0/1: M half (64 rows)
    const int wn = wid >> 1;                         // 0..3: N quarter (32 cols)

    const int ge = blockIdx.z;
    const int gg = ge >> 3, e = ge & 7;
    const int K16 = K >> 4;
    const long row_base = (long)gg * TOKENS + (long)e * CHUNK + (long)blockIdx.y * 128;
    const uint32_t* Abase = A + (size_t)(row_base >> 4) * K16 * 128;
    const uint32_t* Bbase = B + (size_t)(e * (N >> 3) + blockIdx.x * 16) * K16 * 64;

    float* sbias = (float*)(smem + 3 * S_STAGE);
    if (tid < 128) sbias[tid] = bias[e * N + blockIdx.x * 128 + tid];

    const int NK = K >> 6;
    load_stage(sb, Abase, Bbase, K16, 0, tid);
    asm volatile("cp.async.commit_group;" ::: "memory");
    load_stage(sb + S_STAGE, Abase, Bbase, K16, 1, tid);
    asm volatile("cp.async.commit_group;" ::: "memory");

    float acc[4][4][4];
#pragma unroll
    for (int i = 0; i < 4; i++)
#pragma unroll
        for (int j = 0; j < 4; j++)
#pragma unroll
            for (int q = 0; q < 4; q++) acc[i][j][q] = 0.0f;

    for (int kc = 0; kc < NK; kc++) {
        asm volatile("cp.async.wait_group 1;" ::: "memory");   // stage kc complete; kc+1 may fly
        __syncthreads();
        const int nxt = kc + 2;
        if (nxt < NK)
            load_stage(sb + (nxt % 3) * S_STAGE, Abase, Bbase, K16, nxt, tid);
        asm volatile("cp.async.commit_group;" ::: "memory");   // keep group-count invariant

        const uint32_t sA = sb + (kc % 3) * S_STAGE;
        const uint32_t sB = sA + S_A_BYTES;
#pragma unroll
        for (int kt = 0; kt < 4; kt++) {
            uint32_t af[4][4], bf[4][2];
#pragma unroll
            for (int mt = 0; mt < 4; mt++) {
                uint32_t a = sA + (uint32_t)((((wm * 4 + mt) * 4 + kt) * 512) + lid * 16);
                asm volatile("ld.shared.v4.b32 {%0,%1,%2,%3}, [%4];"
                             : "=r"(af[mt][0]), "=r"(af[mt][1]), "=r"(af[mt][2]), "=r"(af[mt][3])
                             : "r"(a));
            }
#pragma unroll
            for (int nt = 0; nt < 4; nt++) {
                uint32_t a = sB + (uint32_t)((((wn * 4 + nt) * 4 + kt) * 256) + lid * 8);
                asm volatile("ld.shared.v2.b32 {%0,%1}, [%2];"
                             : "=r"(bf[nt][0]), "=r"(bf[nt][1]) : "r"(a));
            }
#pragma unroll
            for (int mt = 0; mt < 4; mt++)
#pragma unroll
                for (int nt = 0; nt < 4; nt++)
                    mma_fp16(acc[mt][nt], af[mt], bf[nt]);
        }
    }

    // ---- epilogue ----
#pragma unroll
    for (int mt = 0; mt < 4; mt++) {
        if (GELU) {
            uint32_t* C = (uint32_t*)Cv;
            // Two adjacent nt blocks (16 H-cols) form one fp16 A-frag block of H.
            // Lane's own c-frags pack directly: no shuffles needed.
#pragma unroll
            for (int j = 0; j < 2; j++) {
                float v[2][4];
#pragma unroll
                for (int h = 0; h < 2; h++) {
                    const int nt = 2 * j + h;
                    const int col0 = wn * 32 + nt * 8 + 2 * tt;
#pragma unroll
                    for (int q = 0; q < 4; q++) {
                        float x = acc[mt][nt][q] + sbias[col0 + (q & 1)];
                        x = 0.5f * x * (1.0f + erff(x * 0.70710678118654752f));
                        v[h][q] = x;
                    }
                }
                uint32_t p0 = pack_h2(v[0][0], v[0][1]);   // row gl,   k 2tt,2tt+1
                uint32_t p1 = pack_h2(v[0][2], v[0][3]);   // row gl+8, k 2tt,2tt+1
                uint32_t p2 = pack_h2(v[1][0], v[1][1]);   // row gl,   k 2tt+8,2tt+9
                uint32_t p3 = pack_h2(v[1][2], v[1][3]);   // row gl+8, k 2tt+8,2tt+9
                const size_t Mtile = (size_t)(row_base >> 4) + wm * 4 + mt;
                const int kb2 = blockIdx.x * 8 + wn * 2 + j;
                uint4* dst = reinterpret_cast<uint4*>(
                    C + (Mtile * (size_t)(N >> 4) + kb2) * 128 + lid * 4);
                *dst = make_uint4(p0, p1, p2, p3);
            }
        } else {
            float* C = (float*)Cv;
#pragma unroll
            for (int nt = 0; nt < 4; nt++) {
                const int col0 = wn * 32 + nt * 8 + 2 * tt;
                float v[4];
#pragma unroll
                for (int q = 0; q < 4; q++)
                    v[q] = acc[mt][nt][q] + sbias[col0 + (q & 1)];
                const int r0 = wm * 64 + mt * 16 + gl;
                long R0 = row_base + r0;
                int c = blockIdx.x * 128 + col0;
                *reinterpret_cast<float2*>(&C[(size_t)R0 * N + c]) = make_float2(v[0], v[1]);
                *reinterpret_cast<float2*>(&C[(size_t)(R0 + 8) * N + c]) = make_float2(v[2], v[3]);
            }
        }
    }
}

// ---------------- launch ----------------
extern "C" void kernel_launch(void* const* d_in, const int* in_sizes, int n_in,
                              void* d_out, int out_size) {
    const float* x  = (const float*)d_in[0];
    const float* w1 = (const float*)d_in[1];
    const float* b1 = (const float*)d_in[2];
    const float* w2 = (const float*)d_in[3];
    const float* b2 = (const float*)d_in[4];
    float* out = (float*)d_out;

    uint32_t *p_xr, *p_w1t, *p_w2t, *p_h;
    cudaGetSymbolAddress((void**)&p_xr,  g_xr);
    cudaGetSymbolAddress((void**)&p_w1t, g_w1t);
    cudaGetSymbolAddress((void**)&p_w2t, g_w2t);
    cudaGetSymbolAddress((void**)&p_h,   g_h);

    cudaFuncSetAttribute(gemm_fp16<true>,  cudaFuncAttributeMaxDynamicSharedMemorySize, DSMEM);
    cudaFuncSetAttribute(gemm_fp16<false>, cudaFuncAttributeMaxDynamicSharedMemorySize, DSMEM);

    // pack x into fp16 A-frag layout (65536 rows, K=1024)
    prep_A<<<dim3(D_MODEL / 128, GROUPS * TOKENS / 16), 256>>>(x, p_xr, D_MODEL);
    // pack w1 [e][1024][4096] (k=d_model, n=d_ff) into fp16 B-frag
    prep_B<<<dim3(D_FF / 256, D_MODEL / 16, NUM_EXPERTS), 256>>>(w1, p_w1t, D_MODEL, D_FF);
    // pack w2 [e][4096][1024] (k=d_ff, n=d_model) into fp16 B-frag
    prep_B<<<dim3(D_MODEL / 256, D_FF / 16, NUM_EXPERTS), 256>>>(w2, p_w2t, D_FF, D_MODEL);

    // GEMM1: per (g,e): [2048 x 1024] @ [1024 x 4096] + b1, gelu -> H (fp16 A-frag)
    gemm_fp16<true><<<dim3(D_FF / 128, CHUNK / 128, GROUPS * NUM_EXPERTS), 256, DSMEM>>>(
        p_xr, p_w1t, b1, p_h, D_MODEL, D_FF);
    // GEMM2: per (g,e): [2048 x 4096] @ [4096 x 1024] + b2 -> out (row-major f32)
    gemm_fp16<false><<<dim3(D_MODEL / 128, CHUNK / 128, GROUPS * NUM_EXPERTS), 256, DSMEM>>>(
        p_h, p_w2t, b2, out, D_FF, D_MODEL);
}